// round 1
// baseline (speedup 1.0000x reference)
#include <cuda_runtime.h>
#include <cuda_bf16.h>

// Problem constants
#define Bv  2
#define Sv  2048
#define Dv  512
#define Hv  8
#define HDv 64

// Scratch for projected Q/K/V in head-major layout [B,H,S,HD] (fp32).
// __device__ globals: allocation-free per harness rules. 3 x 8 MB = 24 MB.
__device__ float g_q[Bv * Hv * Sv * HDv];
__device__ float g_k[Bv * Hv * Sv * HDv];
__device__ float g_v[Bv * Hv * Sv * HDv];

// ---------------------------------------------------------------------------
// Kernel 1: QKV projection.  y = x @ W^T + b, written head-major.
// GEMM "NT": x [4096,512] row-major, W [512,512] row-major ([out,in]).
// Tile 64x64, BK=16, 256 threads, 4x4 register microtile per thread.
// blockIdx.z selects which of q/k/v this block computes.
// ---------------------------------------------------------------------------
__global__ __launch_bounds__(256) void proj_kernel(
    const float* __restrict__ x,
    const float* __restrict__ wq, const float* __restrict__ bq,
    const float* __restrict__ wk, const float* __restrict__ bk,
    const float* __restrict__ wv, const float* __restrict__ bv)
{
    const float* w;
    const float* bias;
    float* outp;
    if (blockIdx.z == 0)      { w = wq; bias = bq; outp = g_q; }
    else if (blockIdx.z == 1) { w = wk; bias = bk; outp = g_k; }
    else                      { w = wv; bias = bv; outp = g_v; }

    __shared__ float As[64][16];
    __shared__ float Bs[64][16];

    const int tid = threadIdx.x;
    const int tx  = tid & 15;       // 0..15
    const int ty  = tid >> 4;       // 0..15
    const int m0  = blockIdx.y * 64;
    const int n0  = blockIdx.x * 64;

    const int lr = tid >> 2;        // 0..63  (load row)
    const int lc = (tid & 3) * 4;   // 0,4,8,12 (load col, float4 granule)

    float acc[4][4] = {};

    for (int kt = 0; kt < Dv; kt += 16) {
        float4 av = *(const float4*)&x[(size_t)(m0 + lr) * Dv + kt + lc];
        float4 bv4 = *(const float4*)&w[(size_t)(n0 + lr) * Dv + kt + lc];
        *(float4*)&As[lr][lc] = av;
        *(float4*)&Bs[lr][lc] = bv4;
        __syncthreads();

        #pragma unroll
        for (int kk = 0; kk < 16; kk++) {
            float a[4], b[4];
            #pragma unroll
            for (int i = 0; i < 4; i++) a[i] = As[ty * 4 + i][kk];
            #pragma unroll
            for (int j = 0; j < 4; j++) b[j] = Bs[tx * 4 + j][kk];
            #pragma unroll
            for (int i = 0; i < 4; i++)
                #pragma unroll
                for (int j = 0; j < 4; j++)
                    acc[i][j] += a[i] * b[j];
        }
        __syncthreads();
    }

    // Epilogue: add bias, scatter to head-major [B,H,S,HD].
    // This block covers exactly one head (n0 is a multiple of 64 = HD).
    const int h = n0 / HDv;
    #pragma unroll
    for (int i = 0; i < 4; i++) {
        const int m  = m0 + ty * 4 + i;
        const int b_ = m / Sv;
        const int s  = m % Sv;
        const int hd = tx * 4;                  // column base within head
        float4 r;
        r.x = acc[i][0] + bias[n0 + hd + 0];
        r.y = acc[i][1] + bias[n0 + hd + 1];
        r.z = acc[i][2] + bias[n0 + hd + 2];
        r.w = acc[i][3] + bias[n0 + hd + 3];
        *(float4*)&outp[(((size_t)(b_ * Hv + h)) * Sv + s) * HDv + hd] = r;
    }
}

// ---------------------------------------------------------------------------
// Kernel 2: fused sigmoid attention.
// Per block: one (b,h) pair and one 64-row Q tile.
// Stream K/V in 64-row tiles:  P = sigmoid(Q K^T / 8) -> smem, O += P V.
// The [B,H,S,S] intermediate is never materialized in HBM.
// Dynamic smem: 4 tiles of 64x65 fp32 = 66560 B.
// ---------------------------------------------------------------------------
__global__ __launch_bounds__(256) void attn_kernel(float* __restrict__ out)
{
    extern __shared__ float sm[];
    float (*Qs)[65] = (float(*)[65])(sm);
    float (*Ks)[65] = (float(*)[65])(sm + 64 * 65);
    float (*Vs)[65] = (float(*)[65])(sm + 2 * 64 * 65);
    float (*Ps)[65] = (float(*)[65])(sm + 3 * 64 * 65);

    const int tid = threadIdx.x;
    const int tx  = tid & 15;
    const int ty  = tid >> 4;
    const int qt  = blockIdx.x;     // q tile index, 0..31
    const int bh  = blockIdx.y;     // b*H + h,     0..15

    const float* Qg = g_q + (size_t)bh * Sv * HDv + (size_t)qt * 64 * HDv;
    const float* Kg = g_k + (size_t)bh * Sv * HDv;
    const float* Vg = g_v + (size_t)bh * Sv * HDv;

    // Load Q tile once, pre-scaled by 1/sqrt(HD) = 0.125
    for (int u = tid; u < 64 * 16; u += 256) {
        const int r = u >> 4;
        const int c = (u & 15) * 4;
        float4 v = *(const float4*)&Qg[(size_t)r * HDv + c];
        Qs[r][c + 0] = v.x * 0.125f;
        Qs[r][c + 1] = v.y * 0.125f;
        Qs[r][c + 2] = v.z * 0.125f;
        Qs[r][c + 3] = v.w * 0.125f;
    }

    float o[4][4] = {};

    for (int kt = 0; kt < Sv; kt += 64) {
        __syncthreads();   // protect Ks/Vs (and Qs on first iter) before rewrite
        for (int u = tid; u < 64 * 16; u += 256) {
            const int r = u >> 4;
            const int c = (u & 15) * 4;
            float4 kv = *(const float4*)&Kg[(size_t)(kt + r) * HDv + c];
            float4 vv = *(const float4*)&Vg[(size_t)(kt + r) * HDv + c];
            Ks[r][c + 0] = kv.x; Ks[r][c + 1] = kv.y;
            Ks[r][c + 2] = kv.z; Ks[r][c + 3] = kv.w;
            Vs[r][c + 0] = vv.x; Vs[r][c + 1] = vv.y;
            Vs[r][c + 2] = vv.z; Vs[r][c + 3] = vv.w;
        }
        __syncthreads();

        // P = Q K^T (scaled); Q,K both HD-major -> dot over kk
        float p[4][4] = {};
        #pragma unroll 16
        for (int kk = 0; kk < HDv; kk++) {
            float a[4], b[4];
            #pragma unroll
            for (int i = 0; i < 4; i++) a[i] = Qs[ty * 4 + i][kk];
            #pragma unroll
            for (int j = 0; j < 4; j++) b[j] = Ks[tx * 4 + j][kk];
            #pragma unroll
            for (int i = 0; i < 4; i++)
                #pragma unroll
                for (int j = 0; j < 4; j++)
                    p[i][j] += a[i] * b[j];
        }

        // sigmoid, park in smem for the second GEMM
        #pragma unroll
        for (int i = 0; i < 4; i++)
            #pragma unroll
            for (int j = 0; j < 4; j++)
                Ps[ty * 4 + i][tx * 4 + j] = 1.0f / (1.0f + __expf(-p[i][j]));
        __syncthreads();

        // O += P V
        #pragma unroll 16
        for (int kk = 0; kk < 64; kk++) {
            float a[4], b[4];
            #pragma unroll
            for (int i = 0; i < 4; i++) a[i] = Ps[ty * 4 + i][kk];
            #pragma unroll
            for (int j = 0; j < 4; j++) b[j] = Vs[kk][tx * 4 + j];
            #pragma unroll
            for (int i = 0; i < 4; i++)
                #pragma unroll
                for (int j = 0; j < 4; j++)
                    o[i][j] += a[i] * b[j];
        }
    }

    // Write O to [B,S,D] with heads merged: out[b][s][h*64+hd]
    const int b_ = bh / Hv;
    const int h  = bh % Hv;
    #pragma unroll
    for (int i = 0; i < 4; i++) {
        const int s = qt * 64 + ty * 4 + i;
        float4 r = make_float4(o[i][0], o[i][1], o[i][2], o[i][3]);
        *(float4*)&out[((size_t)(b_ * Sv + s)) * Dv + h * HDv + tx * 4] = r;
    }
}

// ---------------------------------------------------------------------------
extern "C" void kernel_launch(void* const* d_in, const int* in_sizes, int n_in,
                              void* d_out, int out_size)
{
    const float* x  = (const float*)d_in[0];
    const float* wq = (const float*)d_in[1];
    const float* bq = (const float*)d_in[2];
    const float* wk = (const float*)d_in[3];
    const float* bk = (const float*)d_in[4];
    const float* wv = (const float*)d_in[5];
    const float* bv = (const float*)d_in[6];
    float* out = (float*)d_out;

    const int attn_smem = 4 * 64 * 65 * sizeof(float);   // 66560 B > 48 KB default
    cudaFuncSetAttribute(attn_kernel,
                         cudaFuncAttributeMaxDynamicSharedMemorySize, attn_smem);

    dim3 g1(Dv / 64, (Bv * Sv) / 64, 3);   // 8 x 64 x 3 blocks
    proj_kernel<<<g1, 256>>>(x, wq, bq, wk, bk, wv, bv);

    dim3 g2(Sv / 64, Bv * Hv);             // 32 x 16 blocks
    attn_kernel<<<g2, 256, attn_smem>>>(out);
}

// round 4
// speedup vs baseline: 5.3970x; 5.3970x over previous
#include <cuda_runtime.h>
#include <cstdint>

#define Bv  2
#define Sv  2048
#define Dv  512
#define Hv  8
#define HDv 64

// fp32 scratch (allocation-free __device__ globals)
__device__ float g_q [Bv*Hv*Sv*HDv];
__device__ float g_k [Bv*Hv*Sv*HDv];
__device__ float g_v [Bv*Hv*Sv*HDv];
__device__ float g_vt[Bv*Hv*HDv*Sv];   // V transposed: [B,H,HD,S]

// ---------------------------------------------------------------------------
// helpers
// ---------------------------------------------------------------------------
__device__ __forceinline__ void cp16(uint32_t dst, const float* src) {
    asm volatile("cp.async.cg.shared.global [%0], [%1], 16;" :: "r"(dst), "l"(src) : "memory");
}
__device__ __forceinline__ uint32_t smem_u32(const void* p) {
    uint32_t a;
    asm("{ .reg .u64 t; cvta.to.shared.u64 t, %1; cvt.u32.u64 %0, t; }"
        : "=r"(a) : "l"(p));
    return a;
}
__device__ __forceinline__ void cp_commit() { asm volatile("cp.async.commit_group;" ::: "memory"); }
template<int N>
__device__ __forceinline__ void cp_wait() { asm volatile("cp.async.wait_group %0;" :: "n"(N) : "memory"); }

// D += A*B,  m16n8k8 tf32 (fp32-bit regs, HW converts)
__device__ __forceinline__ void mma8(float* d, const uint32_t* a, const uint32_t* b) {
    asm volatile(
        "mma.sync.aligned.m16n8k8.row.col.f32.tf32.tf32.f32 "
        "{%0,%1,%2,%3}, {%4,%5,%6,%7}, {%8,%9}, {%0,%1,%2,%3};"
        : "+f"(d[0]), "+f"(d[1]), "+f"(d[2]), "+f"(d[3])
        : "r"(a[0]), "r"(a[1]), "r"(a[2]), "r"(a[3]), "r"(b[0]), "r"(b[1]));
}

// tf32x3 split: hi exactly representable in tf32, lo = exact fp32 residual
__device__ __forceinline__ void split_tf32(float f, uint32_t& hi, uint32_t& lo) {
    uint32_t h = __float_as_uint(f) & 0xFFFFE000u;
    hi = h;
    lo = __float_as_uint(f - __uint_as_float(h));
}

__device__ __forceinline__ float fast_sigmoid(float x) {   // x already scaled
    float e, r;
    asm("ex2.approx.f32 %0, %1;" : "=f"(e) : "f"(-1.4426950408889634f * x));
    asm("rcp.approx.f32 %0, %1;" : "=f"(r) : "f"(1.0f + e));
    return r;
}

// Stage row-major tile R x C (C%4==0) from gmem (row stride ld) into smem
// laid out with row stride SS floats, via cp.async 16B.
template<int R, int C, int SS, int NT>
__device__ __forceinline__ void stage(uint32_t dst, const float* src, int ld) {
    constexpr int G = C / 4;
    #pragma unroll
    for (int u = 0; u < (R * G + NT - 1) / NT; u++) {
        const int e = u * NT + threadIdx.x;
        if ((R * G) % NT == 0 || e < R * G) {
            const int r = e / G, g = e % G;
            cp16(dst + (uint32_t)(r * SS + g * 4) * 4, src + (size_t)r * ld + g * 4);
        }
    }
}

// ---------------------------------------------------------------------------
// Kernel 1: QKV projection.  C[m][n] = sum_k X[m][k] W[n][k] + b[n]
// block 128x128, 256 thr (8 warps, 2x4 -> warp 64x32), Kc=32 double-buffered.
// tf32x3: hi*hi + lo*hi + hi*lo
// ---------------------------------------------------------------------------
__global__ __launch_bounds__(256) void proj_mma(
    const float* __restrict__ x,
    const float* __restrict__ wq, const float* __restrict__ bq,
    const float* __restrict__ wk, const float* __restrict__ bk,
    const float* __restrict__ wv, const float* __restrict__ bv)
{
    extern __shared__ float sm[];
    // floats: As0=0, As1=4608, Bs0=9216, Bs1=13824  (stride 36)
    const uint32_t sb = smem_u32(sm);
    const int tid = threadIdx.x, wid = tid >> 5, lane = tid & 31;
    const int g = lane >> 2, tg = lane & 3;
    const int wm = (wid >> 2) * 64, wn = (wid & 3) * 32;
    const int m0 = blockIdx.x * 128, n0 = blockIdx.y * 128;

    const float* w; const float* bias; float* outp;
    if (blockIdx.z == 0)      { w = wq; bias = bq; outp = g_q; }
    else if (blockIdx.z == 1) { w = wk; bias = bk; outp = g_k; }
    else                      { w = wv; bias = bv; outp = g_v; }

    float acc[4][4][4] = {};

    stage<128,32,36,256>(sb,            x + (size_t)m0 * Dv, Dv);
    stage<128,32,36,256>(sb + 9216*4,   w + (size_t)n0 * Dv, Dv);
    cp_commit();

    #pragma unroll 1
    for (int kc = 0; kc < 16; kc++) {
        if (kc + 1 < 16) {
            const uint32_t boff = ((kc + 1) & 1) * 4608u * 4u;
            stage<128,32,36,256>(sb + boff,          x + (size_t)m0 * Dv + (kc+1)*32, Dv);
            stage<128,32,36,256>(sb + 9216*4 + boff, w + (size_t)n0 * Dv + (kc+1)*32, Dv);
            cp_commit();
            cp_wait<1>();
        } else cp_wait<0>();
        __syncthreads();

        const float* As = sm + (kc & 1) * 4608;
        const float* Bs = sm + 9216 + (kc & 1) * 4608;
        #pragma unroll
        for (int ks = 0; ks < 4; ks++) {
            const int k0 = ks * 8;
            uint32_t ah[4][4], al[4][4], bh[4][2], bl[4][2];
            #pragma unroll
            for (int i = 0; i < 4; i++) {
                const float* p = As + (wm + i*16 + g) * 36 + k0 + tg;
                split_tf32(p[0],        ah[i][0], al[i][0]);
                split_tf32(p[8*36],     ah[i][1], al[i][1]);
                split_tf32(p[4],        ah[i][2], al[i][2]);
                split_tf32(p[8*36 + 4], ah[i][3], al[i][3]);
            }
            #pragma unroll
            for (int j = 0; j < 4; j++) {
                const float* p = Bs + (wn + j*8 + g) * 36 + k0 + tg;
                split_tf32(p[0], bh[j][0], bl[j][0]);
                split_tf32(p[4], bh[j][1], bl[j][1]);
            }
            #pragma unroll
            for (int i = 0; i < 4; i++)
                #pragma unroll
                for (int j = 0; j < 4; j++) {
                    mma8(acc[i][j], al[i], bh[j]);
                    mma8(acc[i][j], ah[i], bl[j]);
                    mma8(acc[i][j], ah[i], bh[j]);
                }
        }
        __syncthreads();
    }

    // epilogue: bias + head-major scatter [B,H,S,HD]
    #pragma unroll
    for (int i = 0; i < 4; i++) {
        #pragma unroll
        for (int j = 0; j < 4; j++) {
            const int c  = n0 + wn + j*8 + 2*tg;
            const int h  = c >> 6, hd = c & 63;
            const float b0 = bias[c], b1 = bias[c + 1];
            #pragma unroll
            for (int rr = 0; rr < 2; rr++) {
                const int m  = m0 + wm + i*16 + g + rr*8;
                const int b_ = m >> 11, s = m & 2047;
                float2 v = make_float2(acc[i][j][rr*2+0] + b0, acc[i][j][rr*2+1] + b1);
                *(float2*)&outp[(((size_t)(b_ * Hv + h)) * Sv + s) * HDv + hd] = v;
            }
        }
    }
}

// ---------------------------------------------------------------------------
// Kernel 2: transpose g_v [bh][s][hd] -> g_vt [bh][hd][s]
// ---------------------------------------------------------------------------
__global__ void transpose_v() {
    __shared__ float tb[32][33];
    const int bh = blockIdx.z;
    const int s0 = blockIdx.x * 32, h0 = blockIdx.y * 32;
    const float* src = g_v  + (size_t)bh * Sv * HDv;
    float*       dst = g_vt + (size_t)bh * HDv * Sv;
    const int x = threadIdx.x, y = threadIdx.y;
    #pragma unroll
    for (int j = 0; j < 32; j += 8)
        tb[y + j][x] = src[(size_t)(s0 + y + j) * HDv + h0 + x];
    __syncthreads();
    #pragma unroll
    for (int j = 0; j < 32; j += 8)
        dst[(size_t)(h0 + y + j) * Sv + s0 + x] = tb[x][y + j];
}

// ---------------------------------------------------------------------------
// Kernel 3: fused sigmoid attention, tf32x3.
// block: (bh, 128-row q tile), 256 thr (8 warps, 4x2 -> warp 32x32).
// KV streamed in 64-row tiles (double-buffered cp.async):
//   GEMM1: P[128x64] = Q[128x64] . K[64x64]^T   (K-dim = 64)
//   sigmoid(P/8) -> Ps (smem fp32)
//   GEMM2: O[128x64] += Ps[128x64] . Vt[64x64]^T
// ---------------------------------------------------------------------------
__global__ __launch_bounds__(256) void attn_mma(float* __restrict__ out)
{
    extern __shared__ float sm[];
    // floats (stride 68): Qs=0(8704), Ks0=8704, Ks1=13056, Vs0=17408, Vs1=21760, Ps=26112
    const uint32_t sb = smem_u32(sm);
    const int tid = threadIdx.x, wid = tid >> 5, lane = tid & 31;
    const int g = lane >> 2, tg = lane & 3;
    const int wm = (wid >> 1) * 32, wn = (wid & 1) * 32;
    const int qt = blockIdx.x, bh = blockIdx.y;

    const float* Qg  = g_q  + ((size_t)bh * Sv + (size_t)qt * 128) * HDv;
    const float* Kg  = g_k  + (size_t)bh * Sv * HDv;
    const float* Vtg = g_vt + (size_t)bh * HDv * Sv;

    float acc2[2][4][4] = {};

    // prologue: Q + tile 0
    stage<128,64,68,256>(sb,            Qg,  HDv);
    stage<64, 64,68,256>(sb +  8704*4,  Kg,  HDv);
    stage<64, 64,68,256>(sb + 17408*4,  Vtg, Sv);
    cp_commit();

    const int NT = Sv / 64;   // 32
    #pragma unroll 1
    for (int t = 0; t < NT; t++) {
        if (t + 1 < NT) {
            const uint32_t boff = ((t + 1) & 1) * 4352u * 4u;
            stage<64,64,68,256>(sb +  8704*4 + boff, Kg  + (size_t)(t+1) * 64 * HDv, HDv);
            stage<64,64,68,256>(sb + 17408*4 + boff, Vtg + (size_t)(t+1) * 64,       Sv);
            cp_commit();
            cp_wait<1>();
        } else cp_wait<0>();
        __syncthreads();

        const float* Qs = sm;
        const float* Ks = sm +  8704 + (t & 1) * 4352;
        const float* Vs = sm + 17408 + (t & 1) * 4352;
        float*       Ps = sm + 26112;

        // ---- GEMM1: P = Q K^T  (K=64), tf32x3
        float acc1[2][4][4] = {};
        #pragma unroll
        for (int ks = 0; ks < 8; ks++) {
            const int k0 = ks * 8;
            uint32_t ah[2][4], al[2][4], bh[4][2], bl[4][2];
            #pragma unroll
            for (int i = 0; i < 2; i++) {
                const float* p = Qs + (wm + i*16 + g) * 68 + k0 + tg;
                split_tf32(p[0],        ah[i][0], al[i][0]);
                split_tf32(p[8*68],     ah[i][1], al[i][1]);
                split_tf32(p[4],        ah[i][2], al[i][2]);
                split_tf32(p[8*68 + 4], ah[i][3], al[i][3]);
            }
            #pragma unroll
            for (int j = 0; j < 4; j++) {
                const float* p = Ks + (wn + j*8 + g) * 68 + k0 + tg;
                split_tf32(p[0], bh[j][0], bl[j][0]);
                split_tf32(p[4], bh[j][1], bl[j][1]);
            }
            #pragma unroll
            for (int i = 0; i < 2; i++)
                #pragma unroll
                for (int j = 0; j < 4; j++) {
                    mma8(acc1[i][j], al[i], bh[j]);
                    mma8(acc1[i][j], ah[i], bl[j]);
                    mma8(acc1[i][j], ah[i], bh[j]);
                }
        }

        // ---- sigmoid(P * 0.125) -> Ps
        #pragma unroll
        for (int i = 0; i < 2; i++)
            #pragma unroll
            for (int j = 0; j < 4; j++) {
                const int c = wn + j*8 + 2*tg;
                #pragma unroll
                for (int rr = 0; rr < 2; rr++) {
                    const int r = wm + i*16 + g + rr*8;
                    float2 v = make_float2(
                        fast_sigmoid(acc1[i][j][rr*2+0] * 0.125f),
                        fast_sigmoid(acc1[i][j][rr*2+1] * 0.125f));
                    *(float2*)&Ps[r * 68 + c] = v;
                }
            }
        __syncthreads();

        // ---- GEMM2: O += Ps . Vt^T  (K=64), tf32x3
        #pragma unroll
        for (int ks = 0; ks < 8; ks++) {
            const int k0 = ks * 8;
            uint32_t ah[2][4], al[2][4], bh[4][2], bl[4][2];
            #pragma unroll
            for (int i = 0; i < 2; i++) {
                const float* p = Ps + (wm + i*16 + g) * 68 + k0 + tg;
                split_tf32(p[0],        ah[i][0], al[i][0]);
                split_tf32(p[8*68],     ah[i][1], al[i][1]);
                split_tf32(p[4],        ah[i][2], al[i][2]);
                split_tf32(p[8*68 + 4], ah[i][3], al[i][3]);
            }
            #pragma unroll
            for (int j = 0; j < 4; j++) {
                const float* p = Vs + (wn + j*8 + g) * 68 + k0 + tg;
                split_tf32(p[0], bh[j][0], bl[j][0]);
                split_tf32(p[4], bh[j][1], bl[j][1]);
            }
            #pragma unroll
            for (int i = 0; i < 2; i++)
                #pragma unroll
                for (int j = 0; j < 4; j++) {
                    mma8(acc2[i][j], al[i], bh[j]);
                    mma8(acc2[i][j], ah[i], bl[j]);
                    mma8(acc2[i][j], ah[i], bh[j]);
                }
        }
        __syncthreads();
    }

    // ---- write O: out[b][s][h*64+hd]
    const int b_ = bh >> 3, h = bh & 7;
    #pragma unroll
    for (int i = 0; i < 2; i++)
        #pragma unroll
        for (int j = 0; j < 4; j++) {
            const int hd = wn + j*8 + 2*tg;
            #pragma unroll
            for (int rr = 0; rr < 2; rr++) {
                const int s = qt * 128 + wm + i*16 + g + rr*8;
                float2 v = make_float2(acc2[i][j][rr*2+0], acc2[i][j][rr*2+1]);
                *(float2*)&out[((size_t)(b_ * Sv + s)) * Dv + h * HDv + hd] = v;
            }
        }
}

// ---------------------------------------------------------------------------
extern "C" void kernel_launch(void* const* d_in, const int* in_sizes, int n_in,
                              void* d_out, int out_size)
{
    const float* x  = (const float*)d_in[0];
    const float* wq = (const float*)d_in[1];
    const float* bq = (const float*)d_in[2];
    const float* wk = (const float*)d_in[3];
    const float* bk = (const float*)d_in[4];
    const float* wv = (const float*)d_in[5];
    const float* bv = (const float*)d_in[6];
    float* out = (float*)d_out;

    const int proj_smem = 18432 * 4;    // 73728 B
    const int attn_smem = 34816 * 4;    // 139264 B
    cudaFuncSetAttribute(proj_mma, cudaFuncAttributeMaxDynamicSharedMemorySize, proj_smem);
    cudaFuncSetAttribute(attn_mma, cudaFuncAttributeMaxDynamicSharedMemorySize, attn_smem);

    dim3 g1((Bv * Sv) / 128, Dv / 128, 3);
    proj_mma<<<g1, 256, proj_smem>>>(x, wq, bq, wk, bk, wv, bv);

    dim3 g2(Sv / 32, HDv / 32, Bv * Hv);
    transpose_v<<<g2, dim3(32, 8)>>>();

    dim3 g3(Sv / 128, Bv * Hv);
    attn_mma<<<g3, 256, attn_smem>>>(out);
}

// round 5
// speedup vs baseline: 8.0352x; 1.4888x over previous
#include <cuda_runtime.h>
#include <cuda_bf16.h>
#include <cstdint>

#define Bv  2
#define Sv  2048
#define Dv  512
#define Hv  8
#define HDv 64
#define BH  (Bv*Hv)

// Packed bf16 hi/lo scratch (u32 = 2 bf16 along the k dim), allocation-free.
__device__ uint32_t g_qh[BH*Sv*32];            // [bh][s][hd/2]
__device__ uint32_t g_ql[BH*Sv*32];
__device__ uint32_t g_kh[BH*Sv*32];
__device__ uint32_t g_kl[BH*Sv*32];
__device__ float    g_v [BH*Sv*HDv];           // fp32, pre-transpose
__device__ uint32_t g_vth[BH*HDv*(Sv/2)];      // [bh][hd][s/2]
__device__ uint32_t g_vtl[BH*HDv*(Sv/2)];

// ---------------------------------------------------------------------------
// helpers
// ---------------------------------------------------------------------------
__device__ __forceinline__ uint32_t smem_u32(const void* p) {
    uint32_t a;
    asm("{ .reg .u64 t; cvta.to.shared.u64 t, %1; cvt.u32.u64 %0, t; }"
        : "=r"(a) : "l"(p));
    return a;
}
__device__ __forceinline__ void cp16(uint32_t dst, const void* src) {
    asm volatile("cp.async.cg.shared.global [%0], [%1], 16;" :: "r"(dst), "l"(src) : "memory");
}
__device__ __forceinline__ void cp_commit() { asm volatile("cp.async.commit_group;" ::: "memory"); }
template<int N>
__device__ __forceinline__ void cp_wait() { asm volatile("cp.async.wait_group %0;" :: "n"(N) : "memory"); }

// tf32 m16n8k8 (proj mainloop)
__device__ __forceinline__ void mma8(float* d, const uint32_t* a, const uint32_t* b) {
    asm volatile(
        "mma.sync.aligned.m16n8k8.row.col.f32.tf32.tf32.f32 "
        "{%0,%1,%2,%3}, {%4,%5,%6,%7}, {%8,%9}, {%0,%1,%2,%3};"
        : "+f"(d[0]), "+f"(d[1]), "+f"(d[2]), "+f"(d[3])
        : "r"(a[0]), "r"(a[1]), "r"(a[2]), "r"(a[3]), "r"(b[0]), "r"(b[1]));
}
// bf16 m16n8k16 (attn)
__device__ __forceinline__ void mma16(float* d, const uint32_t* a, const uint32_t* b) {
    asm volatile(
        "mma.sync.aligned.m16n8k16.row.col.f32.bf16.bf16.f32 "
        "{%0,%1,%2,%3}, {%4,%5,%6,%7}, {%8,%9}, {%0,%1,%2,%3};"
        : "+f"(d[0]), "+f"(d[1]), "+f"(d[2]), "+f"(d[3])
        : "r"(a[0]), "r"(a[1]), "r"(a[2]), "r"(a[3]), "r"(b[0]), "r"(b[1]));
}

// tf32x3 split (proj)
__device__ __forceinline__ void split_tf32(float f, uint32_t& hi, uint32_t& lo) {
    uint32_t h = __float_as_uint(f) & 0xFFFFE000u;
    hi = h;
    lo = __float_as_uint(f - __uint_as_float(h));
}
// bf16x2 split of pair (f0=lower k, f1=upper k) -> packed hi, packed lo
__device__ __forceinline__ void split2(float f0, float f1, uint32_t& h, uint32_t& l) {
    uint32_t hh;
    asm("cvt.rn.bf16x2.f32 %0, %1, %2;" : "=r"(hh) : "f"(f1), "f"(f0));
    float g0 = __uint_as_float(hh << 16);
    float g1 = __uint_as_float(hh & 0xFFFF0000u);
    asm("cvt.rn.bf16x2.f32 %0, %1, %2;" : "=r"(l) : "f"(f1 - g1), "f"(f0 - g0));
    h = hh;
}

__device__ __forceinline__ float fast_sigmoid(float x) {
    float e, r;
    asm("ex2.approx.f32 %0, %1;" : "=f"(e) : "f"(-1.4426950408889634f * x));
    asm("rcp.approx.f32 %0, %1;" : "=f"(r) : "f"(1.0f + e));
    return r;
}

// fp32 tile stage (proj): R x C floats, smem row stride SS floats
template<int R, int C, int SS, int NT>
__device__ __forceinline__ void stage(uint32_t dst, const float* src, int ld) {
    constexpr int G = C / 4;
    #pragma unroll
    for (int u = 0; u < (R * G) / NT; u++) {
        const int e = u * NT + threadIdx.x;
        const int r = e / G, g = e % G;
        cp16(dst + (uint32_t)(r * SS + g * 4) * 4, src + (size_t)r * ld + g * 4);
    }
}
// u32 tile stage (attn): R rows x C u32, smem row stride ST u32, gmem row stride ld u32
template<int R, int C, int ST, int NT>
__device__ __forceinline__ void stage_u(uint32_t dst, const uint32_t* src, int ld) {
    constexpr int G = C / 4;
    #pragma unroll
    for (int u = 0; u < (R * G) / NT; u++) {
        const int e = u * NT + threadIdx.x;
        const int r = e / G, g = e % G;
        cp16(dst + (uint32_t)(r * ST + g * 4) * 4, src + (size_t)r * ld + g * 4);
    }
}

// ---------------------------------------------------------------------------
// Kernel 1: QKV projection (tf32x3 mainloop).  Epilogue: q,k -> packed bf16
// hi/lo head-major; v -> fp32 head-major.
// ---------------------------------------------------------------------------
__global__ __launch_bounds__(256) void proj_mma(
    const float* __restrict__ x,
    const float* __restrict__ wq, const float* __restrict__ bq,
    const float* __restrict__ wk, const float* __restrict__ bk,
    const float* __restrict__ wv, const float* __restrict__ bv)
{
    extern __shared__ float sm[];
    const uint32_t sb = smem_u32(sm);
    const int tid = threadIdx.x, wid = tid >> 5, lane = tid & 31;
    const int g = lane >> 2, tg = lane & 3;
    const int wm = (wid >> 2) * 64, wn = (wid & 3) * 32;
    const int m0 = blockIdx.x * 128, n0 = blockIdx.y * 128;

    const float* w; const float* bias;
    if (blockIdx.z == 0)      { w = wq; bias = bq; }
    else if (blockIdx.z == 1) { w = wk; bias = bk; }
    else                      { w = wv; bias = bv; }

    float acc[4][4][4] = {};

    stage<128,32,36,256>(sb,          x + (size_t)m0 * Dv, Dv);
    stage<128,32,36,256>(sb + 9216*4, w + (size_t)n0 * Dv, Dv);
    cp_commit();

    #pragma unroll 1
    for (int kc = 0; kc < 16; kc++) {
        cp_wait<0>();
        __syncthreads();
        if (kc + 1 < 16) {
            const uint32_t boff = ((kc + 1) & 1) * 4608u * 4u;
            stage<128,32,36,256>(sb + boff,          x + (size_t)m0 * Dv + (kc+1)*32, Dv);
            stage<128,32,36,256>(sb + 9216*4 + boff, w + (size_t)n0 * Dv + (kc+1)*32, Dv);
            cp_commit();
        }
        const float* As = sm + (kc & 1) * 4608;
        const float* Bs = sm + 9216 + (kc & 1) * 4608;
        #pragma unroll
        for (int ks = 0; ks < 4; ks++) {
            const int k0 = ks * 8;
            uint32_t ah[4][4], al[4][4], bh[4][2], bl[4][2];
            #pragma unroll
            for (int i = 0; i < 4; i++) {
                const float* p = As + (wm + i*16 + g) * 36 + k0 + tg;
                split_tf32(p[0],        ah[i][0], al[i][0]);
                split_tf32(p[8*36],     ah[i][1], al[i][1]);
                split_tf32(p[4],        ah[i][2], al[i][2]);
                split_tf32(p[8*36 + 4], ah[i][3], al[i][3]);
            }
            #pragma unroll
            for (int j = 0; j < 4; j++) {
                const float* p = Bs + (wn + j*8 + g) * 36 + k0 + tg;
                split_tf32(p[0], bh[j][0], bl[j][0]);
                split_tf32(p[4], bh[j][1], bl[j][1]);
            }
            #pragma unroll
            for (int i = 0; i < 4; i++)
                #pragma unroll
                for (int j = 0; j < 4; j++) {
                    mma8(acc[i][j], al[i], bh[j]);
                    mma8(acc[i][j], ah[i], bl[j]);
                    mma8(acc[i][j], ah[i], bh[j]);
                }
        }
        __syncthreads();
    }

    // epilogue
    const int z = blockIdx.z;
    uint32_t* outh = (z == 0) ? g_qh : g_kh;
    uint32_t* outl = (z == 0) ? g_ql : g_kl;
    #pragma unroll
    for (int i = 0; i < 4; i++) {
        #pragma unroll
        for (int j = 0; j < 4; j++) {
            const int c  = n0 + wn + j*8 + 2*tg;     // even
            const int h  = c >> 6, hd = c & 63;
            const float b0 = bias[c], b1 = bias[c + 1];
            #pragma unroll
            for (int rr = 0; rr < 2; rr++) {
                const int m  = m0 + wm + i*16 + g + rr*8;
                const int b_ = m >> 11, s = m & 2047;
                const float f0 = acc[i][j][rr*2+0] + b0;
                const float f1 = acc[i][j][rr*2+1] + b1;
                if (z == 2) {
                    *(float2*)&g_v[(((size_t)(b_ * Hv + h)) * Sv + s) * HDv + hd] =
                        make_float2(f0, f1);
                } else {
                    uint32_t hp, lp;
                    split2(f0, f1, hp, lp);
                    const size_t idx = (((size_t)(b_ * Hv + h)) * Sv + s) * 32 + (hd >> 1);
                    outh[idx] = hp;
                    outl[idx] = lp;
                }
            }
        }
    }
}

// ---------------------------------------------------------------------------
// Kernel 2: transpose + bf16-split V:  g_v[bh][s][hd] -> g_vth/g_vtl[bh][hd][s/2]
// ---------------------------------------------------------------------------
__global__ __launch_bounds__(256) void prep_v() {
    __shared__ float tb[32][33];
    const int bh = blockIdx.z;
    const int s0 = blockIdx.x * 32, h0 = blockIdx.y * 32;
    const int tid = threadIdx.x;
    #pragma unroll
    for (int u = 0; u < 4; u++) {
        const int idx = u * 256 + tid;
        const int sl = idx >> 5, hl = idx & 31;
        tb[sl][hl] = g_v[((size_t)bh * Sv + s0 + sl) * HDv + h0 + hl];
    }
    __syncthreads();
    #pragma unroll
    for (int u = 0; u < 2; u++) {
        const int o = u * 256 + tid;
        const int hl = o >> 4, xp = o & 15;
        uint32_t h, l;
        split2(tb[2*xp][hl], tb[2*xp+1][hl], h, l);
        const size_t oi = ((size_t)bh * HDv + h0 + hl) * (Sv/2) + (s0 >> 1) + xp;
        g_vth[oi] = h;
        g_vtl[oi] = l;
    }
}

// ---------------------------------------------------------------------------
// Kernel 3: fused sigmooid attention, bf16x2 3-term.
// block: (bh, 128-row q tile), 256 thr, 8 warps = 4 row-groups x 2 K-halves.
// Per 64-row KV tile:
//   GEMM1: P[32x32]/warp = Q.K^T (k=64, bf16x2) -> acc1 regs
//   sigmoid(acc1/8) -> bf16x2 A-fragments IN REGISTERS (layout identity)
//   GEMM2: O[32x64]/warp += P_sig . Vt^T over this warp's 32-col K slice
// Final: cross-warp-pair O reduction in smem.
// smem u32 (stride 36 = 32 data + 4 pad): Qh 0, Ql 4608, Kh 9216(+2304*buf),
// Kl 13824, Vh 18432, Vl 23040.  Total 27648 u32 = 110592 B.
// ---------------------------------------------------------------------------
__global__ __launch_bounds__(256) void attn_mma(float* __restrict__ out)
{
    extern __shared__ uint32_t su[];
    const uint32_t sb = smem_u32(su);
    const int tid = threadIdx.x, wid = tid >> 5, lane = tid & 31;
    const int g = lane >> 2, tg = lane & 3;
    const int wm = (wid >> 1) * 32;
    const int wk2 = wid & 1, wn = wk2 * 32;
    const int qt = blockIdx.x, bh = blockIdx.y;

    const uint32_t* Qhg = g_qh + ((size_t)bh * Sv + (size_t)qt * 128) * 32;
    const uint32_t* Qlg = g_ql + ((size_t)bh * Sv + (size_t)qt * 128) * 32;
    const uint32_t* Khg = g_kh + (size_t)bh * Sv * 32;
    const uint32_t* Klg = g_kl + (size_t)bh * Sv * 32;
    const uint32_t* Vhg = g_vth + (size_t)bh * HDv * (Sv/2);
    const uint32_t* Vlg = g_vtl + (size_t)bh * HDv * (Sv/2);

    float acc2[2][8][4] = {};

    // prologue: Q + tile 0 (single cp.async group)
    stage_u<128,32,36,256>(sb,           Qhg, 32);
    stage_u<128,32,36,256>(sb +  4608*4, Qlg, 32);
    stage_u<64, 32,36,256>(sb +  9216*4, Khg, 32);
    stage_u<64, 32,36,256>(sb + 13824*4, Klg, 32);
    stage_u<64, 32,36,256>(sb + 18432*4, Vhg, Sv/2);
    stage_u<64, 32,36,256>(sb + 23040*4, Vlg, Sv/2);
    cp_commit();

    const int NT = Sv / 64;   // 32
    #pragma unroll 1
    for (int t = 0; t < NT; t++) {
        cp_wait<0>();
        __syncthreads();
        if (t + 1 < NT) {
            const uint32_t boff = ((t + 1) & 1) * 2304u * 4u;
            stage_u<64,32,36,256>(sb +  9216*4 + boff, Khg + (size_t)(t+1) * 64 * 32, 32);
            stage_u<64,32,36,256>(sb + 13824*4 + boff, Klg + (size_t)(t+1) * 64 * 32, 32);
            stage_u<64,32,36,256>(sb + 18432*4 + boff, Vhg + (size_t)(t+1) * 32,      Sv/2);
            stage_u<64,32,36,256>(sb + 23040*4 + boff, Vlg + (size_t)(t+1) * 32,      Sv/2);
            cp_commit();
        }

        const uint32_t* Qh = su;
        const uint32_t* Ql = su + 4608;
        const uint32_t* Kh = su +  9216 + (t & 1) * 2304;
        const uint32_t* Kl = su + 13824 + (t & 1) * 2304;
        const uint32_t* Vh = su + 18432 + (t & 1) * 2304;
        const uint32_t* Vl = su + 23040 + (t & 1) * 2304;

        // ---- GEMM1: P = Q K^T  (k = 64 = 4 chunks of 16)
        float acc1[2][4][4] = {};
        #pragma unroll
        for (int ks = 0; ks < 4; ks++) {
            const int c0 = ks * 8 + tg;
            uint32_t ah[2][4], al[2][4], bhf[4][2], blf[4][2];
            #pragma unroll
            for (int i = 0; i < 2; i++) {
                const int base = (wm + i*16 + g) * 36 + c0;
                ah[i][0] = Qh[base];          al[i][0] = Ql[base];
                ah[i][1] = Qh[base + 8*36];   al[i][1] = Ql[base + 8*36];
                ah[i][2] = Qh[base + 4];      al[i][2] = Ql[base + 4];
                ah[i][3] = Qh[base + 8*36+4]; al[i][3] = Ql[base + 8*36+4];
            }
            #pragma unroll
            for (int j = 0; j < 4; j++) {
                const int nb = (wn + j*8 + g) * 36 + c0;
                bhf[j][0] = Kh[nb];     blf[j][0] = Kl[nb];
                bhf[j][1] = Kh[nb + 4]; blf[j][1] = Kl[nb + 4];
            }
            #pragma unroll
            for (int i = 0; i < 2; i++)
                #pragma unroll
                for (int j = 0; j < 4; j++) {
                    mma16(acc1[i][j], al[i], bhf[j]);
                    mma16(acc1[i][j], ah[i], blf[j]);
                    mma16(acc1[i][j], ah[i], bhf[j]);
                }
        }

        // ---- sigmoid(P/8) -> bf16x2 A fragments (register-only, layout identity)
        uint32_t ph[2][2][4], pl[2][2][4];
        #pragma unroll
        for (int i = 0; i < 2; i++)
            #pragma unroll
            for (int ks2 = 0; ks2 < 2; ks2++) {
                const int j0 = 2*ks2, j1 = 2*ks2 + 1;
                split2(fast_sigmoid(acc1[i][j0][0] * 0.125f),
                       fast_sigmoid(acc1[i][j0][1] * 0.125f), ph[i][ks2][0], pl[i][ks2][0]);
                split2(fast_sigmoid(acc1[i][j0][2] * 0.125f),
                       fast_sigmoid(acc1[i][j0][3] * 0.125f), ph[i][ks2][1], pl[i][ks2][1]);
                split2(fast_sigmoid(acc1[i][j1][0] * 0.125f),
                       fast_sigmoid(acc1[i][j1][1] * 0.125f), ph[i][ks2][2], pl[i][ks2][2]);
                split2(fast_sigmoid(acc1[i][j1][2] * 0.125f),
                       fast_sigmoid(acc1[i][j1][3] * 0.125f), ph[i][ks2][3], pl[i][ks2][3]);
            }

        // ---- GEMM2: O += P_sig . Vt^T over this warp's K slice (wn..wn+32)
        #pragma unroll
        for (int ks2 = 0; ks2 < 2; ks2++) {
            const int vc = (wn >> 1) + ks2 * 8 + tg;
            #pragma unroll
            for (int j2 = 0; j2 < 8; j2++) {
                const int nb = (j2*8 + g) * 36 + vc;
                uint32_t vbh[2] = { Vh[nb], Vh[nb + 4] };
                uint32_t vbl[2] = { Vl[nb], Vl[nb + 4] };
                #pragma unroll
                for (int i = 0; i < 2; i++) {
                    mma16(acc2[i][j2], pl[i][ks2], vbh);
                    mma16(acc2[i][j2], ph[i][ks2], vbl);
                    mma16(acc2[i][j2], ph[i][ks2], vbh);
                }
            }
        }
    }

    // ---- cross-warp-pair O reduction (region reuses dead Q tiles)
    float* smf = (float*)su;
    __syncthreads();
    if (wk2 == 1) {
        #pragma unroll
        for (int i = 0; i < 2; i++)
            #pragma unroll
            for (int j2 = 0; j2 < 8; j2++)
                #pragma unroll
                for (int rr = 0; rr < 2; rr++) {
                    const int r = wm + i*16 + g + rr*8;
                    *(float2*)&smf[r * 68 + j2*8 + 2*tg] =
                        make_float2(acc2[i][j2][rr*2+0], acc2[i][j2][rr*2+1]);
                }
    }
    __syncthreads();
    if (wk2 == 0) {
        const int b_ = bh >> 3, h = bh & 7;
        #pragma unroll
        for (int i = 0; i < 2; i++)
            #pragma unroll
            for (int j2 = 0; j2 < 8; j2++)
                #pragma unroll
                for (int rr = 0; rr < 2; rr++) {
                    const int r = wm + i*16 + g + rr*8;
                    float2 o = *(float2*)&smf[r * 68 + j2*8 + 2*tg];
                    o.x += acc2[i][j2][rr*2+0];
                    o.y += acc2[i][j2][rr*2+1];
                    const int s = qt * 128 + r;
                    *(float2*)&out[((size_t)(b_ * Sv + s)) * Dv + h * HDv + j2*8 + 2*tg] = o;
                }
    }
}

// ---------------------------------------------------------------------------
extern "C" void kernel_launch(void* const* d_in, const int* in_sizes, int n_in,
                              void* d_out, int out_size)
{
    const float* x  = (const float*)d_in[0];
    const float* wq = (const float*)d_in[1];
    const float* bq = (const float*)d_in[2];
    const float* wk = (const float*)d_in[3];
    const float* bk = (const float*)d_in[4];
    const float* wv = (const float*)d_in[5];
    const float* bv = (const float*)d_in[6];
    float* out = (float*)d_out;

    const int proj_smem = 18432 * 4;    // 73728 B
    const int attn_smem = 27648 * 4;    // 110592 B
    cudaFuncSetAttribute(proj_mma, cudaFuncAttributeMaxDynamicSharedMemorySize, proj_smem);
    cudaFuncSetAttribute(attn_mma, cudaFuncAttributeMaxDynamicSharedMemorySize, attn_smem);

    dim3 g1((Bv * Sv) / 128, Dv / 128, 3);
    proj_mma<<<g1, 256, proj_smem>>>(x, wq, bq, wk, bk, wv, bv);

    dim3 g2(Sv / 32, HDv / 32, BH);
    prep_v<<<g2, 256>>>();

    dim3 g3(Sv / 128, BH);
    attn_mma<<<g3, 256, attn_smem>>>(out);
}

// round 6
// speedup vs baseline: 10.6666x; 1.3275x over previous
#include <cuda_runtime.h>
#include <cuda_bf16.h>
#include <cstdint>

#define Bv  2
#define Sv  2048
#define Dv  512
#define Hv  8
#define HDv 64
#define BH  16

// Scratch (allocation-free __device__ globals)
__device__ uint32_t g_xh[4096*256], g_xl[4096*256];     // x split, bf16 pairs along D
__device__ uint32_t g_wh[3*512*256], g_wl[3*512*256];   // wq|wk|wv split
__device__ uint32_t g_qh[BH*Sv*32];                     // Q fp16 pairs along HD
__device__ uint32_t g_kh[BH*Sv*32];                     // K fp16 pairs along HD
__device__ float    g_v [BH*Sv*HDv];                    // V fp32 head-major
__device__ uint32_t g_vth[BH*HDv*(Sv/2)];               // Vt bf16-hi pairs along S
__device__ uint32_t g_vtl[BH*HDv*(Sv/2)];               // Vt bf16-lo

// ---------------------------------------------------------------------------
// helpers
// ---------------------------------------------------------------------------
__device__ __forceinline__ uint32_t smem_u32(const void* p) {
    uint32_t a;
    asm("{ .reg .u64 t; cvta.to.shared.u64 t, %1; cvt.u32.u64 %0, t; }"
        : "=r"(a) : "l"(p));
    return a;
}
__device__ __forceinline__ void cp16(uint32_t dst, const void* src) {
    asm volatile("cp.async.cg.shared.global [%0], [%1], 16;" :: "r"(dst), "l"(src) : "memory");
}
__device__ __forceinline__ void cp_commit() { asm volatile("cp.async.commit_group;" ::: "memory"); }
template<int N>
__device__ __forceinline__ void cp_wait() { asm volatile("cp.async.wait_group %0;" :: "n"(N) : "memory"); }

// bf16 m16n8k16
__device__ __forceinline__ void mma16b(float* d, const uint32_t* a, const uint32_t* b) {
    asm volatile(
        "mma.sync.aligned.m16n8k16.row.col.f32.bf16.bf16.f32 "
        "{%0,%1,%2,%3}, {%4,%5,%6,%7}, {%8,%9}, {%0,%1,%2,%3};"
        : "+f"(d[0]), "+f"(d[1]), "+f"(d[2]), "+f"(d[3])
        : "r"(a[0]), "r"(a[1]), "r"(a[2]), "r"(a[3]), "r"(b[0]), "r"(b[1]));
}
// fp16 m16n8k16
__device__ __forceinline__ void mma16f(float* d, const uint32_t* a, const uint32_t* b) {
    asm volatile(
        "mma.sync.aligned.m16n8k16.row.col.f32.f16.f16.f32 "
        "{%0,%1,%2,%3}, {%4,%5,%6,%7}, {%8,%9}, {%0,%1,%2,%3};"
        : "+f"(d[0]), "+f"(d[1]), "+f"(d[2]), "+f"(d[3])
        : "r"(a[0]), "r"(a[1]), "r"(a[2]), "r"(a[3]), "r"(b[0]), "r"(b[1]));
}

// bf16x2 split: f0=even k, f1=odd k -> packed hi, packed lo
__device__ __forceinline__ void split2(float f0, float f1, uint32_t& h, uint32_t& l) {
    uint32_t hh;
    asm("cvt.rn.bf16x2.f32 %0, %1, %2;" : "=r"(hh) : "f"(f1), "f"(f0));
    float g0 = __uint_as_float(hh << 16);
    float g1 = __uint_as_float(hh & 0xFFFF0000u);
    asm("cvt.rn.bf16x2.f32 %0, %1, %2;" : "=r"(l) : "f"(f1 - g1), "f"(f0 - g0));
    h = hh;
}
// fp16 pack (no residual)
__device__ __forceinline__ uint32_t pack_f16(float f0, float f1) {
    uint32_t h;
    asm("cvt.rn.f16x2.f32 %0, %1, %2;" : "=r"(h) : "f"(f1), "f"(f0));
    return h;
}

// 4 sigmoids sharing one rcp: s[q] = sigmoid(x[q] * 0.125)
__device__ __forceinline__ void sigmoid4(const float* x, float* s) {
    float a[4];
    #pragma unroll
    for (int q = 0; q < 4; q++) {
        float e;
        asm("ex2.approx.f32 %0, %1;" : "=f"(e) : "f"(x[q] * (-0.125f * 1.4426950408889634f)));
        a[q] = 1.0f + e;
    }
    const float p01 = a[0] * a[1], p23 = a[2] * a[3];
    float r;
    asm("rcp.approx.f32 %0, %1;" : "=f"(r) : "f"(p01 * p23));
    const float r01 = r * p23, r23 = r * p01;
    s[0] = r01 * a[1]; s[1] = r01 * a[0];
    s[2] = r23 * a[3]; s[3] = r23 * a[2];
}

// u32 tile stage: R rows x 32 u32, smem row stride 36 u32, gmem stride ld u32
template<int R, int NT>
__device__ __forceinline__ void stage_u(uint32_t dst, const uint32_t* src, int ld) {
    #pragma unroll
    for (int u = 0; u < (R * 8) / NT; u++) {
        const int e = u * NT + threadIdx.x;
        const int r = e >> 3, g = e & 7;
        cp16(dst + (uint32_t)(r * 36 + g * 4) * 4, src + (size_t)r * ld + g * 4);
    }
}

// ---------------------------------------------------------------------------
// Kernel 0: split x and w into packed bf16 hi/lo
// ---------------------------------------------------------------------------
__global__ __launch_bounds__(256) void prep_xw(
    const float* __restrict__ x,  const float* __restrict__ wq,
    const float* __restrict__ wk, const float* __restrict__ wv)
{
    const uint32_t XN = 4096u * 256u, WN = 512u * 256u;
    const uint32_t i = blockIdx.x * 256u + threadIdx.x;
    float2 f; uint32_t *oh, *ol; uint32_t o;
    if (i < XN) { f = ((const float2*)x)[i]; oh = g_xh; ol = g_xl; o = i; }
    else {
        const uint32_t j = i - XN;
        const float* w = (j < WN) ? wq : (j < 2u*WN) ? wk : wv;
        f = ((const float2*)w)[j % WN]; oh = g_wh; ol = g_wl; o = j;
    }
    uint32_t h, l;
    split2(f.x, f.y, h, l);
    oh[o] = h; ol[o] = l;
}

// ---------------------------------------------------------------------------
// Kernel 1: QKV projection, bf16x2 3-term.  512 thr, 16 warps (4x4), warp 32x32.
// smem u32 (stride 36): per buffer Xh 0, Xl 4608, Wh 9216, Wl 13824; buf stride 18432.
// ---------------------------------------------------------------------------
__global__ __launch_bounds__(512) void proj_mma(
    const float* __restrict__ bq, const float* __restrict__ bk,
    const float* __restrict__ bv)
{
    extern __shared__ uint32_t su[];
    const uint32_t sb = smem_u32(su);
    const int tid = threadIdx.x, wid = tid >> 5, lane = tid & 31;
    const int g = lane >> 2, tg = lane & 3;
    const int wm = (wid >> 2) * 32, wn = (wid & 3) * 32;
    const int m0 = blockIdx.x * 128, n0 = blockIdx.y * 128;
    const int z  = blockIdx.z;
    const float* bias = (z == 0) ? bq : (z == 1) ? bk : bv;

    const uint32_t* Xh_g = g_xh + (size_t)m0 * 256;
    const uint32_t* Xl_g = g_xl + (size_t)m0 * 256;
    const uint32_t* Wh_g = g_wh + ((size_t)z * 512 + n0) * 256;
    const uint32_t* Wl_g = g_wl + ((size_t)z * 512 + n0) * 256;

    float acc[2][4][4] = {};

    stage_u<128,512>(sb,            Xh_g, 256);
    stage_u<128,512>(sb +  4608*4,  Xl_g, 256);
    stage_u<128,512>(sb +  9216*4,  Wh_g, 256);
    stage_u<128,512>(sb + 13824*4,  Wl_g, 256);
    cp_commit();

    #pragma unroll 1
    for (int kc = 0; kc < 8; kc++) {
        cp_wait<0>();
        __syncthreads();
        if (kc + 1 < 8) {
            const uint32_t bo = ((kc + 1) & 1) * 18432u * 4u;
            const int co = (kc + 1) * 32;
            stage_u<128,512>(sb + bo,            Xh_g + co, 256);
            stage_u<128,512>(sb + bo +  4608*4,  Xl_g + co, 256);
            stage_u<128,512>(sb + bo +  9216*4,  Wh_g + co, 256);
            stage_u<128,512>(sb + bo + 13824*4,  Wl_g + co, 256);
            cp_commit();
        }
        const uint32_t* Xh = su + (kc & 1) * 18432;
        const uint32_t* Xl = Xh + 4608;
        const uint32_t* Wh = Xh + 9216;
        const uint32_t* Wl = Xh + 13824;

        #pragma unroll
        for (int ks = 0; ks < 4; ks++) {
            const int c0 = ks * 8 + tg;
            uint32_t ah[2][4], al[2][4], bh[4][2], bl[4][2];
            #pragma unroll
            for (int i = 0; i < 2; i++) {
                const int base = (wm + i*16 + g) * 36 + c0;
                ah[i][0] = Xh[base];       al[i][0] = Xl[base];
                ah[i][1] = Xh[base + 288]; al[i][1] = Xl[base + 288];
                ah[i][2] = Xh[base + 4];   al[i][2] = Xl[base + 4];
                ah[i][3] = Xh[base + 292]; al[i][3] = Xl[base + 292];
            }
            #pragma unroll
            for (int j = 0; j < 4; j++) {
                const int nb = (wn + j*8 + g) * 36 + c0;
                bh[j][0] = Wh[nb];     bl[j][0] = Wl[nb];
                bh[j][1] = Wh[nb + 4]; bl[j][1] = Wl[nb + 4];
            }
            #pragma unroll
            for (int i = 0; i < 2; i++)
                #pragma unroll
                for (int j = 0; j < 4; j++) {
                    mma16b(acc[i][j], al[i], bh[j]);
                    mma16b(acc[i][j], ah[i], bl[j]);
                    mma16b(acc[i][j], ah[i], bh[j]);
                }
        }
    }

    // epilogue: bias, head-major scatter.  q/k -> fp16 packed; v -> fp32.
    #pragma unroll
    for (int i = 0; i < 2; i++) {
        #pragma unroll
        for (int j = 0; j < 4; j++) {
            const int c  = n0 + wn + j*8 + 2*tg;
            const int h  = c >> 6, hd = c & 63;
            const float b0 = bias[c], b1 = bias[c + 1];
            #pragma unroll
            for (int rr = 0; rr < 2; rr++) {
                const int m  = m0 + wm + i*16 + g + rr*8;
                const int b_ = m >> 11, s = m & 2047;
                const float f0 = acc[i][j][rr*2+0] + b0;
                const float f1 = acc[i][j][rr*2+1] + b1;
                if (z == 2) {
                    *(float2*)&g_v[(((size_t)(b_ * Hv + h)) * Sv + s) * HDv + hd] =
                        make_float2(f0, f1);
                } else {
                    uint32_t* o = (z == 0) ? g_qh : g_kh;
                    o[(((size_t)(b_ * Hv + h)) * Sv + s) * 32 + (hd >> 1)] = pack_f16(f0, f1);
                }
            }
        }
    }
}

// ---------------------------------------------------------------------------
// Kernel 2: transpose + bf16-split V:  g_v[bh][s][hd] -> g_vth/g_vtl[bh][hd][s/2]
// ---------------------------------------------------------------------------
__global__ __launch_bounds__(256) void prep_v() {
    __shared__ float tb[32][33];
    const int bh = blockIdx.z;
    const int s0 = blockIdx.x * 32, h0 = blockIdx.y * 32;
    const int tid = threadIdx.x;
    #pragma unroll
    for (int u = 0; u < 4; u++) {
        const int idx = u * 256 + tid;
        const int sl = idx >> 5, hl = idx & 31;
        tb[sl][hl] = g_v[((size_t)bh * Sv + s0 + sl) * HDv + h0 + hl];
    }
    __syncthreads();
    #pragma unroll
    for (int u = 0; u < 2; u++) {
        const int o = u * 256 + tid;
        const int hl = o >> 4, xp = o & 15;
        uint32_t h, l;
        split2(tb[2*xp][hl], tb[2*xp+1][hl], h, l);
        const size_t oi = ((size_t)bh * HDv + h0 + hl) * (Sv/2) + (s0 >> 1) + xp;
        g_vth[oi] = h;
        g_vtl[oi] = l;
    }
}

// ---------------------------------------------------------------------------
// Kernel 3: fused sigmoid attention.  512 thr, 16 warps = 4 row x 4 KV-quarter.
// Per 64-row KV tile:
//   GEMM1: P[32x16]/warp = Q.K^T, SINGLE fp16 mma (k=64)
//   sigmoid (batched rcp) -> bf16x2 split in registers
//   GEMM2: O[32x64]/warp += P_sig . Vt^T over warp's 16-KV slice, bf16x2 3-term
// Final: 4-way cross-warp O reduction via smem.
// smem u32 (stride 36): Qh 0 (4608), Kh 4608+2304b, Vh 9216+2304b, Vl 13824+2304b.
// Total 18432 u32 = 73728 B.
// ---------------------------------------------------------------------------
__global__ __launch_bounds__(512) void attn_mma(float* __restrict__ out)
{
    extern __shared__ uint32_t su[];
    const uint32_t sb = smem_u32(su);
    const int tid = threadIdx.x, wid = tid >> 5, lane = tid & 31;
    const int g = lane >> 2, tg = lane & 3;
    const int wm = (wid >> 2) * 32;      // row group
    const int wc = wid & 3;              // KV quarter (16 cols)
    const int qt = blockIdx.x, bh = blockIdx.y;

    const uint32_t* Qhg = g_qh + ((size_t)bh * Sv + (size_t)qt * 128) * 32;
    const uint32_t* Khg = g_kh + (size_t)bh * Sv * 32;
    const uint32_t* Vhg = g_vth + (size_t)bh * HDv * (Sv/2);
    const uint32_t* Vlg = g_vtl + (size_t)bh * HDv * (Sv/2);

    float acc2[2][8][4] = {};

    stage_u<128,512>(sb,           Qhg, 32);
    stage_u<64, 512>(sb +  4608*4, Khg, 32);
    stage_u<64, 512>(sb +  9216*4, Vhg, Sv/2);
    stage_u<64, 512>(sb + 13824*4, Vlg, Sv/2);
    cp_commit();

    const int NT = Sv / 64;   // 32
    #pragma unroll 1
    for (int t = 0; t < NT; t++) {
        cp_wait<0>();
        __syncthreads();
        if (t + 1 < NT) {
            const uint32_t bo = ((t + 1) & 1) * 2304u * 4u;
            stage_u<64,512>(sb +  4608*4 + bo, Khg + (size_t)(t+1) * 64 * 32, 32);
            stage_u<64,512>(sb +  9216*4 + bo, Vhg + (size_t)(t+1) * 32,      Sv/2);
            stage_u<64,512>(sb + 13824*4 + bo, Vlg + (size_t)(t+1) * 32,      Sv/2);
            cp_commit();
        }
        const uint32_t* Qh = su;
        const uint32_t* Kh = su +  4608 + (t & 1) * 2304;
        const uint32_t* Vh = su +  9216 + (t & 1) * 2304;
        const uint32_t* Vl = su + 13824 + (t & 1) * 2304;

        // ---- GEMM1: P = Q K^T  (single fp16 mma per k16 chunk)
        float acc1[2][2][4] = {};
        #pragma unroll
        for (int ks = 0; ks < 4; ks++) {
            const int c0 = ks * 8 + tg;
            uint32_t ah[2][4], bhf[2][2];
            #pragma unroll
            for (int i = 0; i < 2; i++) {
                const int base = (wm + i*16 + g) * 36 + c0;
                ah[i][0] = Qh[base];
                ah[i][1] = Qh[base + 288];
                ah[i][2] = Qh[base + 4];
                ah[i][3] = Qh[base + 292];
            }
            #pragma unroll
            for (int j = 0; j < 2; j++) {
                const int nb = (wc*16 + j*8 + g) * 36 + c0;
                bhf[j][0] = Kh[nb];
                bhf[j][1] = Kh[nb + 4];
            }
            #pragma unroll
            for (int i = 0; i < 2; i++)
                #pragma unroll
                for (int j = 0; j < 2; j++)
                    mma16f(acc1[i][j], ah[i], bhf[j]);
        }

        // ---- sigmoid(P/8) -> bf16x2 A fragments (register-only)
        uint32_t ph[2][4], pl[2][4];
        #pragma unroll
        for (int i = 0; i < 2; i++)
            #pragma unroll
            for (int j = 0; j < 2; j++) {
                float s[4];
                sigmoid4(acc1[i][j], s);
                split2(s[0], s[1], ph[i][j*2+0], pl[i][j*2+0]);
                split2(s[2], s[3], ph[i][j*2+1], pl[i][j*2+1]);
            }

        // ---- GEMM2: O += P_sig . Vt^T over warp's 16-KV slice (bf16x2 3-term)
        #pragma unroll
        for (int j2 = 0; j2 < 8; j2++) {
            const int nb = (j2*8 + g) * 36 + wc*8 + tg;
            uint32_t vbh[2] = { Vh[nb], Vh[nb + 4] };
            uint32_t vbl[2] = { Vl[nb], Vl[nb + 4] };
            #pragma unroll
            for (int i = 0; i < 2; i++) {
                mma16b(acc2[i][j2], pl[i], vbh);
                mma16b(acc2[i][j2], ph[i], vbl);
                mma16b(acc2[i][j2], ph[i], vbh);
            }
        }
    }

    // ---- 4-way cross-warp O reduction (smem reuses dead operand tiles)
    float* smf = (float*)su;                   // buf0 @0, buf1 @8704 (stride 68)
    __syncthreads();
    if (wc == 1 || wc == 3) {
        float* buf = smf + (wc == 3 ? 8704 : 0);
        #pragma unroll
        for (int i = 0; i < 2; i++)
            #pragma unroll
            for (int j2 = 0; j2 < 8; j2++)
                #pragma unroll
                for (int rr = 0; rr < 2; rr++) {
                    const int r = wm + i*16 + g + rr*8;
                    *(float2*)&buf[r * 68 + j2*8 + 2*tg] =
                        make_float2(acc2[i][j2][rr*2+0], acc2[i][j2][rr*2+1]);
                }
    }
    __syncthreads();
    if (wc == 0 || wc == 2) {
        const float* buf = smf + (wc == 2 ? 8704 : 0);
        #pragma unroll
        for (int i = 0; i < 2; i++)
            #pragma unroll
            for (int j2 = 0; j2 < 8; j2++)
                #pragma unroll
                for (int rr = 0; rr < 2; rr++) {
                    const int r = wm + i*16 + g + rr*8;
                    float2 v = *(const float2*)&buf[r * 68 + j2*8 + 2*tg];
                    acc2[i][j2][rr*2+0] += v.x;
                    acc2[i][j2][rr*2+1] += v.y;
                }
    }
    __syncthreads();
    if (wc == 2) {
        #pragma unroll
        for (int i = 0; i < 2; i++)
            #pragma unroll
            for (int j2 = 0; j2 < 8; j2++)
                #pragma unroll
                for (int rr = 0; rr < 2; rr++) {
                    const int r = wm + i*16 + g + rr*8;
                    *(float2*)&smf[r * 68 + j2*8 + 2*tg] =
                        make_float2(acc2[i][j2][rr*2+0], acc2[i][j2][rr*2+1]);
                }
    }
    __syncthreads();
    if (wc == 0) {
        const int b_ = bh >> 3, h = bh & 7;
        #pragma unroll
        for (int i = 0; i < 2; i++)
            #pragma unroll
            for (int j2 = 0; j2 < 8; j2++)
                #pragma unroll
                for (int rr = 0; rr < 2; rr++) {
                    const int r = wm + i*16 + g + rr*8;
                    float2 v = *(const float2*)&smf[r * 68 + j2*8 + 2*tg];
                    v.x += acc2[i][j2][rr*2+0];
                    v.y += acc2[i][j2][rr*2+1];
                    const int s = qt * 128 + r;
                    *(float2*)&out[((size_t)(b_ * Sv + s)) * Dv + h * HDv + j2*8 + 2*tg] = v;
                }
    }
}

// ---------------------------------------------------------------------------
extern "C" void kernel_launch(void* const* d_in, const int* in_sizes, int n_in,
                              void* d_out, int out_size)
{
    const float* x  = (const float*)d_in[0];
    const float* wq = (const float*)d_in[1];
    const float* bq = (const float*)d_in[2];
    const float* wk = (const float*)d_in[3];
    const float* bk = (const float*)d_in[4];
    const float* wv = (const float*)d_in[5];
    const float* bv = (const float*)d_in[6];
    float* out = (float*)d_out;

    const int proj_smem = 36864 * 4;    // 147456 B
    const int attn_smem = 18432 * 4;    // 73728 B
    cudaFuncSetAttribute(proj_mma, cudaFuncAttributeMaxDynamicSharedMemorySize, proj_smem);
    cudaFuncSetAttribute(attn_mma, cudaFuncAttributeMaxDynamicSharedMemorySize, attn_smem);

    prep_xw<<<5632, 256>>>(x, wq, wk, wv);

    dim3 g1((Bv * Sv) / 128, Dv / 128, 3);
    proj_mma<<<g1, 512, proj_smem>>>(bq, bk, bv);

    dim3 g2(Sv / 32, HDv / 32, BH);
    prep_v<<<g2, 256>>>();

    dim3 g3(Sv / 128, BH);
    attn_mma<<<g3, 512, attn_smem>>>(out);
}

// round 7
// speedup vs baseline: 13.5705x; 1.2722x over previous
#include <cuda_runtime.h>
#include <cuda_bf16.h>
#include <cstdint>

#define Bv  2
#define Sv  2048
#define Dv  512
#define Hv  8
#define HDv 64
#define BH  16

// Scratch (allocation-free __device__ globals)
__device__ uint32_t g_xh[4096*256], g_xl[4096*256];     // x split, bf16 pairs along D
__device__ uint32_t g_wh[3*512*256], g_wl[3*512*256];   // wq|wk|wv split
__device__ uint32_t g_qh[BH*Sv*32];                     // Q fp16 pairs along HD
__device__ uint32_t g_kh[BH*Sv*32];                     // K fp16 pairs along HD
__device__ float    g_v [BH*Sv*HDv];                    // V fp32 head-major
__device__ uint32_t g_vt[BH*HDv*(Sv/2)];                // Vt fp16 pairs along S

// ---------------------------------------------------------------------------
// helpers
// ---------------------------------------------------------------------------
__device__ __forceinline__ uint32_t smem_u32(const void* p) {
    uint32_t a;
    asm("{ .reg .u64 t; cvta.to.shared.u64 t, %1; cvt.u32.u64 %0, t; }"
        : "=r"(a) : "l"(p));
    return a;
}
__device__ __forceinline__ void cp16(uint32_t dst, const void* src) {
    asm volatile("cp.async.cg.shared.global [%0], [%1], 16;" :: "r"(dst), "l"(src) : "memory");
}
__device__ __forceinline__ void cp_commit() { asm volatile("cp.async.commit_group;" ::: "memory"); }
template<int N>
__device__ __forceinline__ void cp_wait() { asm volatile("cp.async.wait_group %0;" :: "n"(N) : "memory"); }

// bf16 m16n8k16
__device__ __forceinline__ void mma16b(float* d, const uint32_t* a, const uint32_t* b) {
    asm volatile(
        "mma.sync.aligned.m16n8k16.row.col.f32.bf16.bf16.f32 "
        "{%0,%1,%2,%3}, {%4,%5,%6,%7}, {%8,%9}, {%0,%1,%2,%3};"
        : "+f"(d[0]), "+f"(d[1]), "+f"(d[2]), "+f"(d[3])
        : "r"(a[0]), "r"(a[1]), "r"(a[2]), "r"(a[3]), "r"(b[0]), "r"(b[1]));
}
// fp16 m16n8k16
__device__ __forceinline__ void mma16f(float* d, const uint32_t* a, const uint32_t* b) {
    asm volatile(
        "mma.sync.aligned.m16n8k16.row.col.f32.f16.f16.f32 "
        "{%0,%1,%2,%3}, {%4,%5,%6,%7}, {%8,%9}, {%0,%1,%2,%3};"
        : "+f"(d[0]), "+f"(d[1]), "+f"(d[2]), "+f"(d[3])
        : "r"(a[0]), "r"(a[1]), "r"(a[2]), "r"(a[3]), "r"(b[0]), "r"(b[1]));
}

// bf16x2 split: f0=even k, f1=odd k -> packed hi, packed lo
__device__ __forceinline__ void split2(float f0, float f1, uint32_t& h, uint32_t& l) {
    uint32_t hh;
    asm("cvt.rn.bf16x2.f32 %0, %1, %2;" : "=r"(hh) : "f"(f1), "f"(f0));
    float g0 = __uint_as_float(hh << 16);
    float g1 = __uint_as_float(hh & 0xFFFF0000u);
    asm("cvt.rn.bf16x2.f32 %0, %1, %2;" : "=r"(l) : "f"(f1 - g1), "f"(f0 - g0));
    h = hh;
}
// fp16 pack
__device__ __forceinline__ uint32_t pack_f16(float f0, float f1) {
    uint32_t h;
    asm("cvt.rn.f16x2.f32 %0, %1, %2;" : "=r"(h) : "f"(f1), "f"(f0));
    return h;
}

// 4 sigmoids sharing one rcp: s[q] = sigmoid(x[q] * 0.125)
__device__ __forceinline__ void sigmoid4(const float* x, float* s) {
    float a[4];
    #pragma unroll
    for (int q = 0; q < 4; q++) {
        float e;
        asm("ex2.approx.f32 %0, %1;" : "=f"(e) : "f"(x[q] * (-0.125f * 1.4426950408889634f)));
        a[q] = 1.0f + e;
    }
    const float p01 = a[0] * a[1], p23 = a[2] * a[3];
    float r;
    asm("rcp.approx.f32 %0, %1;" : "=f"(r) : "f"(p01 * p23));
    const float r01 = r * p23, r23 = r * p01;
    s[0] = r01 * a[1]; s[1] = r01 * a[0];
    s[2] = r23 * a[3]; s[3] = r23 * a[2];
}

// u32 tile stage: R rows x C u32 cols, smem row stride ST u32, gmem stride ld u32
template<int R, int C, int ST, int NT>
__device__ __forceinline__ void stage_u(uint32_t dst, const uint32_t* src, int ld) {
    constexpr int G = C / 4;
    #pragma unroll
    for (int u = 0; u < (R * G) / NT; u++) {
        const int e = u * NT + threadIdx.x;
        const int r = e / G, g = e % G;
        cp16(dst + (uint32_t)(r * ST + g * 4) * 4, src + (size_t)r * ld + g * 4);
    }
}

// ---------------------------------------------------------------------------
// Kernel 0: split x and w into packed bf16 hi/lo
// ---------------------------------------------------------------------------
__global__ __launch_bounds__(256) void prep_xw(
    const float* __restrict__ x,  const float* __restrict__ wq,
    const float* __restrict__ wk, const float* __restrict__ wv)
{
    const uint32_t XN = 4096u * 256u, WN = 512u * 256u;
    const uint32_t i = blockIdx.x * 256u + threadIdx.x;
    float2 f; uint32_t *oh, *ol; uint32_t o;
    if (i < XN) { f = ((const float2*)x)[i]; oh = g_xh; ol = g_xl; o = i; }
    else {
        const uint32_t j = i - XN;
        const float* w = (j < WN) ? wq : (j < 2u*WN) ? wk : wv;
        f = ((const float2*)w)[j % WN]; oh = g_wh; ol = g_wl; o = j;
    }
    uint32_t h, l;
    split2(f.x, f.y, h, l);
    oh[o] = h; ol[o] = l;
}

// ---------------------------------------------------------------------------
// Kernel 1: QKV projection, bf16x2 3-term.  512 thr, 16 warps (4x4), warp 32x32.
// (unchanged from round 6)
// ---------------------------------------------------------------------------
__global__ __launch_bounds__(512) void proj_mma(
    const float* __restrict__ bq, const float* __restrict__ bk,
    const float* __restrict__ bv)
{
    extern __shared__ uint32_t su[];
    const uint32_t sb = smem_u32(su);
    const int tid = threadIdx.x, wid = tid >> 5, lane = tid & 31;
    const int g = lane >> 2, tg = lane & 3;
    const int wm = (wid >> 2) * 32, wn = (wid & 3) * 32;
    const int m0 = blockIdx.x * 128, n0 = blockIdx.y * 128;
    const int z  = blockIdx.z;
    const float* bias = (z == 0) ? bq : (z == 1) ? bk : bv;

    const uint32_t* Xh_g = g_xh + (size_t)m0 * 256;
    const uint32_t* Xl_g = g_xl + (size_t)m0 * 256;
    const uint32_t* Wh_g = g_wh + ((size_t)z * 512 + n0) * 256;
    const uint32_t* Wl_g = g_wl + ((size_t)z * 512 + n0) * 256;

    float acc[2][4][4] = {};

    stage_u<128,32,36,512>(sb,            Xh_g, 256);
    stage_u<128,32,36,512>(sb +  4608*4,  Xl_g, 256);
    stage_u<128,32,36,512>(sb +  9216*4,  Wh_g, 256);
    stage_u<128,32,36,512>(sb + 13824*4,  Wl_g, 256);
    cp_commit();

    #pragma unroll 1
    for (int kc = 0; kc < 8; kc++) {
        cp_wait<0>();
        __syncthreads();
        if (kc + 1 < 8) {
            const uint32_t bo = ((kc + 1) & 1) * 18432u * 4u;
            const int co = (kc + 1) * 32;
            stage_u<128,32,36,512>(sb + bo,            Xh_g + co, 256);
            stage_u<128,32,36,512>(sb + bo +  4608*4,  Xl_g + co, 256);
            stage_u<128,32,36,512>(sb + bo +  9216*4,  Wh_g + co, 256);
            stage_u<128,32,36,512>(sb + bo + 13824*4,  Wl_g + co, 256);
            cp_commit();
        }
        const uint32_t* Xh = su + (kc & 1) * 18432;
        const uint32_t* Xl = Xh + 4608;
        const uint32_t* Wh = Xh + 9216;
        const uint32_t* Wl = Xh + 13824;

        #pragma unroll
        for (int ks = 0; ks < 4; ks++) {
            const int c0 = ks * 8 + tg;
            uint32_t ah[2][4], al[2][4], bh[4][2], bl[4][2];
            #pragma unroll
            for (int i = 0; i < 2; i++) {
                const int base = (wm + i*16 + g) * 36 + c0;
                ah[i][0] = Xh[base];       al[i][0] = Xl[base];
                ah[i][1] = Xh[base + 288]; al[i][1] = Xl[base + 288];
                ah[i][2] = Xh[base + 4];   al[i][2] = Xl[base + 4];
                ah[i][3] = Xh[base + 292]; al[i][3] = Xl[base + 292];
            }
            #pragma unroll
            for (int j = 0; j < 4; j++) {
                const int nb = (wn + j*8 + g) * 36 + c0;
                bh[j][0] = Wh[nb];     bl[j][0] = Wl[nb];
                bh[j][1] = Wh[nb + 4]; bl[j][1] = Wl[nb + 4];
            }
            #pragma unroll
            for (int i = 0; i < 2; i++)
                #pragma unroll
                for (int j = 0; j < 4; j++) {
                    mma16b(acc[i][j], al[i], bh[j]);
                    mma16b(acc[i][j], ah[i], bl[j]);
                    mma16b(acc[i][j], ah[i], bh[j]);
                }
        }
    }

    // epilogue: bias, head-major scatter.  q/k -> fp16 packed; v -> fp32.
    #pragma unroll
    for (int i = 0; i < 2; i++) {
        #pragma unroll
        for (int j = 0; j < 4; j++) {
            const int c  = n0 + wn + j*8 + 2*tg;
            const int h  = c >> 6, hd = c & 63;
            const float b0 = bias[c], b1 = bias[c + 1];
            #pragma unroll
            for (int rr = 0; rr < 2; rr++) {
                const int m  = m0 + wm + i*16 + g + rr*8;
                const int b_ = m >> 11, s = m & 2047;
                const float f0 = acc[i][j][rr*2+0] + b0;
                const float f1 = acc[i][j][rr*2+1] + b1;
                if (z == 2) {
                    *(float2*)&g_v[(((size_t)(b_ * Hv + h)) * Sv + s) * HDv + hd] =
                        make_float2(f0, f1);
                } else {
                    uint32_t* o = (z == 0) ? g_qh : g_kh;
                    o[(((size_t)(b_ * Hv + h)) * Sv + s) * 32 + (hd >> 1)] = pack_f16(f0, f1);
                }
            }
        }
    }
}

// ---------------------------------------------------------------------------
// Kernel 2: transpose + fp16-pack V:  g_v[bh][s][hd] -> g_vt[bh][hd][s/2]
// ---------------------------------------------------------------------------
__global__ __launch_bounds__(256) void prep_v() {
    __shared__ float tb[32][33];
    const int bh = blockIdx.z;
    const int s0 = blockIdx.x * 32, h0 = blockIdx.y * 32;
    const int tid = threadIdx.x;
    #pragma unroll
    for (int u = 0; u < 4; u++) {
        const int idx = u * 256 + tid;
        const int sl = idx >> 5, hl = idx & 31;
        tb[sl][hl] = g_v[((size_t)bh * Sv + s0 + sl) * HDv + h0 + hl];
    }
    __syncthreads();
    #pragma unroll
    for (int u = 0; u < 2; u++) {
        const int o = u * 256 + tid;
        const int hl = o >> 4, xp = o & 15;
        g_vt[((size_t)bh * HDv + h0 + hl) * (Sv/2) + (s0 >> 1) + xp] =
            pack_f16(tb[2*xp][hl], tb[2*xp+1][hl]);
    }
}

// ---------------------------------------------------------------------------
// Kernel 3: fused sigmoid attention, all-fp16 MMA.
// block: (bh, 64-row q tile), 256 thr, 8 warps = 2 row-groups x 4 KV-quarters.
// 2 blocks/SM (smem 80896 B, regs capped at 128).
// Per 128-row KV tile, per warp (32 q rows x 32 KV cols), per 16-KV chunk kc:
//   GEMM1: P[32x16] = Q.K^T (fp16, k=64)            8 MMAs
//   sigmoid (batched rcp) -> fp16 A-frags in regs
//   GEMM2: O[32x64] += P_sig . Vt^T (fp16, k=16)    16 MMAs
// Final: 4-way cross-warp O reduction via smem.
// smem u32: Qh 0 (64x36=2304), Kh 2304 + buf*4608 (128x36), Vt 11520 + buf*4352 (64x68).
// Total 20224 u32 = 80896 B.
// ---------------------------------------------------------------------------
__global__ __launch_bounds__(256, 2) void attn_mma(float* __restrict__ out)
{
    extern __shared__ uint32_t su[];
    const uint32_t sb = smem_u32(su);
    const int tid = threadIdx.x, wid = tid >> 5, lane = tid & 31;
    const int g = lane >> 2, tg = lane & 3;
    const int wm = (wid >> 2) * 32;      // row group (0 or 32)
    const int wc = wid & 3;              // KV quarter (32 cols)
    const int qt = blockIdx.x, bh = blockIdx.y;

    const uint32_t* Qhg = g_qh + ((size_t)bh * Sv + (size_t)qt * 64) * 32;
    const uint32_t* Khg = g_kh + (size_t)bh * Sv * 32;
    const uint32_t* Vtg = g_vt + (size_t)bh * HDv * (Sv/2);

    float acc2[2][8][4] = {};

    stage_u<64, 32,36,256>(sb,           Qhg, 32);
    stage_u<128,32,36,256>(sb +  2304*4, Khg, 32);
    stage_u<64, 64,68,256>(sb + 11520*4, Vtg, Sv/2);
    cp_commit();

    const int NT = Sv / 128;   // 16
    #pragma unroll 1
    for (int t = 0; t < NT; t++) {
        cp_wait<0>();
        __syncthreads();
        if (t + 1 < NT) {
            const uint32_t bk = ((t + 1) & 1) * 4608u * 4u;
            const uint32_t bv = ((t + 1) & 1) * 4352u * 4u;
            stage_u<128,32,36,256>(sb +  2304*4 + bk, Khg + (size_t)(t+1) * 128 * 32, 32);
            stage_u<64, 64,68,256>(sb + 11520*4 + bv, Vtg + (size_t)(t+1) * 64,       Sv/2);
            cp_commit();
        }
        const uint32_t* Qh = su;
        const uint32_t* Kh = su +  2304 + (t & 1) * 4608;
        const uint32_t* Vt = su + 11520 + (t & 1) * 4352;

        #pragma unroll
        for (int kc = 0; kc < 2; kc++) {
            // ---- GEMM1: P[32x16] = Q K^T  (k=64, 4 chunks)
            float acc1[2][2][4] = {};
            #pragma unroll
            for (int ks = 0; ks < 4; ks++) {
                const int c0 = ks * 8 + tg;
                uint32_t af[2][4], bf[2][2];
                #pragma unroll
                for (int i = 0; i < 2; i++) {
                    const int base = (wm + i*16 + g) * 36 + c0;
                    af[i][0] = Qh[base];
                    af[i][1] = Qh[base + 288];
                    af[i][2] = Qh[base + 4];
                    af[i][3] = Qh[base + 292];
                }
                #pragma unroll
                for (int j = 0; j < 2; j++) {
                    const int nb = (wc*32 + kc*16 + j*8 + g) * 36 + c0;
                    bf[j][0] = Kh[nb];
                    bf[j][1] = Kh[nb + 4];
                }
                #pragma unroll
                for (int i = 0; i < 2; i++)
                    #pragma unroll
                    for (int j = 0; j < 2; j++)
                        mma16f(acc1[i][j], af[i], bf[j]);
            }

            // ---- sigmoid(P/8) -> fp16 A fragments (register-only)
            uint32_t pa[2][4];
            #pragma unroll
            for (int i = 0; i < 2; i++) {
                float s0[4], s1[4];
                sigmoid4(acc1[i][0], s0);
                sigmoid4(acc1[i][1], s1);
                pa[i][0] = pack_f16(s0[0], s0[1]);
                pa[i][1] = pack_f16(s0[2], s0[3]);
                pa[i][2] = pack_f16(s1[0], s1[1]);
                pa[i][3] = pack_f16(s1[2], s1[3]);
            }

            // ---- GEMM2: O += P_sig . Vt^T  (k = this 16-KV chunk)
            const int vc = wc*16 + kc*8 + tg;
            #pragma unroll
            for (int j2 = 0; j2 < 8; j2++) {
                const int nb = (j2*8 + g) * 68 + vc;
                uint32_t vb[2] = { Vt[nb], Vt[nb + 4] };
                #pragma unroll
                for (int i = 0; i < 2; i++)
                    mma16f(acc2[i][j2], pa[i], vb);
            }
        }
    }

    // ---- 4-way cross-warp O reduction (smem reuses dead operand tiles)
    float* smf = (float*)su;                   // buf0 @0, buf1 @4352 (stride 68)
    __syncthreads();
    if (wc == 1 || wc == 3) {
        float* buf = smf + (wc == 3 ? 4352 : 0);
        #pragma unroll
        for (int i = 0; i < 2; i++)
            #pragma unroll
            for (int j2 = 0; j2 < 8; j2++)
                #pragma unroll
                for (int rr = 0; rr < 2; rr++) {
                    const int r = wm + i*16 + g + rr*8;
                    *(float2*)&buf[r * 68 + j2*8 + 2*tg] =
                        make_float2(acc2[i][j2][rr*2+0], acc2[i][j2][rr*2+1]);
                }
    }
    __syncthreads();
    if (wc == 0 || wc == 2) {
        const float* buf = smf + (wc == 2 ? 4352 : 0);
        #pragma unroll
        for (int i = 0; i < 2; i++)
            #pragma unroll
            for (int j2 = 0; j2 < 8; j2++)
                #pragma unroll
                for (int rr = 0; rr < 2; rr++) {
                    const int r = wm + i*16 + g + rr*8;
                    float2 v = *(const float2*)&buf[r * 68 + j2*8 + 2*tg];
                    acc2[i][j2][rr*2+0] += v.x;
                    acc2[i][j2][rr*2+1] += v.y;
                }
    }
    __syncthreads();
    if (wc == 2) {
        #pragma unroll
        for (int i = 0; i < 2; i++)
            #pragma unroll
            for (int j2 = 0; j2 < 8; j2++)
                #pragma unroll
                for (int rr = 0; rr < 2; rr++) {
                    const int r = wm + i*16 + g + rr*8;
                    *(float2*)&smf[r * 68 + j2*8 + 2*tg] =
                        make_float2(acc2[i][j2][rr*2+0], acc2[i][j2][rr*2+1]);
                }
    }
    __syncthreads();
    if (wc == 0) {
        const int b_ = bh >> 3, h = bh & 7;
        #pragma unroll
        for (int i = 0; i < 2; i++)
            #pragma unroll
            for (int j2 = 0; j2 < 8; j2++)
                #pragma unroll
                for (int rr = 0; rr < 2; rr++) {
                    const int r = wm + i*16 + g + rr*8;
                    float2 v = *(const float2*)&smf[r * 68 + j2*8 + 2*tg];
                    v.x += acc2[i][j2][rr*2+0];
                    v.y += acc2[i][j2][rr*2+1];
                    const int s = qt * 64 + r;
                    *(float2*)&out[((size_t)(b_ * Sv + s)) * Dv + h * HDv + j2*8 + 2*tg] = v;
                }
    }
}

// ---------------------------------------------------------------------------
extern "C" void kernel_launch(void* const* d_in, const int* in_sizes, int n_in,
                              void* d_out, int out_size)
{
    const float* x  = (const float*)d_in[0];
    const float* wq = (const float*)d_in[1];
    const float* bq = (const float*)d_in[2];
    const float* wk = (const float*)d_in[3];
    const float* bk = (const float*)d_in[4];
    const float* wv = (const float*)d_in[5];
    const float* bv = (const float*)d_in[6];
    float* out = (float*)d_out;

    const int proj_smem = 36864 * 4;    // 147456 B
    const int attn_smem = 20224 * 4;    // 80896 B
    cudaFuncSetAttribute(proj_mma, cudaFuncAttributeMaxDynamicSharedMemorySize, proj_smem);
    cudaFuncSetAttribute(attn_mma, cudaFuncAttributeMaxDynamicSharedMemorySize, attn_smem);

    prep_xw<<<5632, 256>>>(x, wq, wk, wv);

    dim3 g1((Bv * Sv) / 128, Dv / 128, 3);
    proj_mma<<<g1, 512, proj_smem>>>(bq, bk, bv);

    dim3 g2(Sv / 32, HDv / 32, BH);
    prep_v<<<g2, 256>>>();

    dim3 g3(Sv / 64, BH);
    attn_mma<<<g3, 256, attn_smem>>>(out);
}